// round 12
// baseline (speedup 1.0000x reference)
#include <cuda_runtime.h>

// Problem constants: x (16,800,256), mu (64,256), prec (64) -> out (16, 64*256)
#define BB 16
#define TT 800
#define DD 256
#define KK 64
#define NSLOT 25  // 25 blocks of 32 rows per batch -> grid 400, occupancy 2
#define NR 32
#define PX 68     // smem pitch for sx/smu (16B-aligned rows, conflict-free)
#define PG 65     // smem pitch for sG (kills STS bank conflicts in dump)

typedef unsigned long long ull;

// ---------------- scratch (device globals) --------------------------------------
// g_acc zero at load; finalize re-zeros after reading (invariant across replays).
__device__ float g_acc[BB * KK * DD];
__device__ float g_Ssl[BB * NSLOT * KK];

// ---------------- f32x2 / RED helpers -------------------------------------------
__device__ __forceinline__ ull pack2(float lo, float hi) {
    ull r; asm("mov.b64 %0,{%1,%2};" : "=l"(r) : "f"(lo), "f"(hi)); return r;
}
__device__ __forceinline__ ull fma2(ull a, ull b, ull c) {
    ull d; asm("fma.rn.f32x2 %0,%1,%2,%3;" : "=l"(d) : "l"(a), "l"(b), "l"(c)); return d;
}
__device__ __forceinline__ float2 unpack2(ull v) {
    float2 f; asm("mov.b64 {%0,%1},%2;" : "=f"(f.x), "=f"(f.y) : "l"(v)); return f;
}
__device__ __forceinline__ void red_add_v4(float* p, float x, float y, float z, float w) {
    asm volatile("red.global.add.v4.f32 [%0], {%1,%2,%3,%4};"
                 :: "l"(p), "f"(x), "f"(y), "f"(z), "f"(w) : "memory");
}

union F4 { float4 f; ull u[2]; };

// smem layout (floats):
//   sx    [0, 2176)        NR*PX
//   smu   [2176, 6528)     64*PX
//   sr    [8192, 10240)    NR*64   (above the 32KB phase-C window? see below)
//   sxsq  [10240, 10272)
//   smusq [10272, 10336)
//   sS    [10336, 10848)
// Phase C double buffers: bytes [0,16384) and [16384,32768) = floats [0,8192)
//   -> sr at float 8192 is untouched by phase C. sG overlays sx (NR*PG <= 2176).
#define SOFF_SMU   2176
#define SOFF_SR    8192
#define SOFF_XSQ   10240
#define SOFF_MUSQ  10272
#define SOFF_SS    10336
#define FUSED_SMEM (10848 * 4)

__global__ __launch_bounds__(256, 2)
void fused_kernel(const float* __restrict__ x, const float* __restrict__ mu,
                  const float* __restrict__ prec) {
    extern __shared__ char sm[];
    float* sx    = (float*)sm;
    float* smu   = (float*)sm + SOFF_SMU;
    float* sr    = (float*)sm + SOFF_SR;
    float* sxsq  = (float*)sm + SOFF_XSQ;
    float* smusq = (float*)sm + SOFF_MUSQ;
    float* sS    = (float*)sm + SOFF_SS;
    float* sG    = sx;                      // phase B overlay

    int bx   = blockIdx.x;                  // 400 blocks
    int b    = bx / NSLOT;
    int slot = bx - b * NSLOT;
    int trow0 = b * TT + slot * NR;

    int tid  = threadIdx.x;
    int lane = tid & 31;
    int w    = tid >> 5;

    const float4* x4  = (const float4*)x;
    const float4* mu4 = (const float4*)mu;

    // ---- Phase A: G[32 x 64] = X * MU^T ----
    // warp w owns k in [8w, 8w+8); lane owns row = lane. acc = 8 f32x2.
    ull acc[8];
    #pragma unroll
    for (int i = 0; i < 8; i++) acc[i] = 0ull;
    float myxsq[2] = {0.f, 0.f};
    float mymusq[4] = {0.f, 0.f, 0.f, 0.f};

    float4 px[2], pm[4];
    #pragma unroll
    for (int ii = 0; ii < 2; ii++) {
        int idx = tid + 256 * ii;
        px[ii] = x4[(trow0 + (idx >> 4)) * 64 + (idx & 15)];
    }
    #pragma unroll
    for (int ii = 0; ii < 4; ii++) {
        int idx = tid + 256 * ii;
        pm[ii] = mu4[(idx >> 4) * 64 + (idx & 15)];
    }

    for (int c = 0; c < 4; c++) {
        __syncthreads();
        #pragma unroll
        for (int ii = 0; ii < 2; ii++) {
            int idx = tid + 256 * ii;
            float4 v = px[ii];
            myxsq[ii] += v.x * v.x + v.y * v.y + v.z * v.z + v.w * v.w;
            *(float4*)(sx + (idx >> 4) * PX + 4 * (idx & 15)) = v;
        }
        #pragma unroll
        for (int ii = 0; ii < 4; ii++) {
            int idx = tid + 256 * ii;
            float4 m = pm[ii];
            mymusq[ii] += m.x * m.x + m.y * m.y + m.z * m.z + m.w * m.w;
            *(float4*)(smu + (idx >> 4) * PX + 4 * (idx & 15)) = m;
        }
        __syncthreads();
        if (c < 3) {
            #pragma unroll
            for (int ii = 0; ii < 2; ii++) {
                int idx = tid + 256 * ii;
                px[ii] = x4[(trow0 + (idx >> 4)) * 64 + (c + 1) * 16 + (idx & 15)];
            }
            #pragma unroll
            for (int ii = 0; ii < 4; ii++) {
                int idx = tid + 256 * ii;
                pm[ii] = mu4[(idx >> 4) * 64 + (c + 1) * 16 + (idx & 15)];
            }
        }
        #pragma unroll 4
        for (int q = 0; q < 16; q++) {
            F4 mv[8], xv;
            #pragma unroll
            for (int j = 0; j < 8; j++)
                mv[j].f = *(const float4*)(smu + (w * 8 + j) * PX + 4 * q);  // broadcast
            xv.f = *(const float4*)(sx + lane * PX + 4 * q);
            #pragma unroll
            for (int j = 0; j < 8; j++) {
                acc[j] = fma2(xv.u[0], mv[j].u[0], acc[j]);
                acc[j] = fma2(xv.u[1], mv[j].u[1], acc[j]);
            }
        }
    }

    // reduce xsq / musq across 16 threads sharing a staging row
    #pragma unroll
    for (int o = 1; o < 16; o <<= 1) {
        #pragma unroll
        for (int ii = 0; ii < 2; ii++)
            myxsq[ii] += __shfl_xor_sync(0xffffffffu, myxsq[ii], o);
        #pragma unroll
        for (int ii = 0; ii < 4; ii++)
            mymusq[ii] += __shfl_xor_sync(0xffffffffu, mymusq[ii], o);
    }
    __syncthreads();   // all reads of sx done before sG overlay
    if ((tid & 15) == 0) {
        #pragma unroll
        for (int ii = 0; ii < 2; ii++) sxsq[(tid >> 4) + 16 * ii] = myxsq[ii];
        #pragma unroll
        for (int ii = 0; ii < 4; ii++) smusq[(tid >> 4) + 16 * ii] = mymusq[ii];
    }

    // dump G (overlay on sx, pitch PG)
    #pragma unroll
    for (int j = 0; j < 8; j++) {
        float2 v = unpack2(acc[j]);
        sG[lane * PG + w * 8 + j] = v.x + v.y;
    }
    __syncthreads();

    // ---- Phase B: softmax over K=64, 4 rows per warp ----
    {
        float p0 = prec[lane], p1 = prec[lane + 32];
        float pp0 = p0 * p0, pp1 = p1 * p1;
        float mq0 = smusq[lane], mq1 = smusq[lane + 32];

        float l0[4], l1[4], mx[4], sms[4];
        #pragma unroll
        for (int rr = 0; rr < 4; rr++) {
            int row = w * 4 + rr;
            float xq = sxsq[row];
            float G0 = sG[row * PG + lane];
            float G1 = sG[row * PG + lane + 32];
            l0[rr] = -pp0 * (xq - 2.f * G0 + mq0);
            l1[rr] = -pp1 * (xq - 2.f * G1 + mq1);
            mx[rr] = fmaxf(l0[rr], l1[rr]);
        }
        #pragma unroll
        for (int o = 16; o; o >>= 1)
            #pragma unroll
            for (int rr = 0; rr < 4; rr++)
                mx[rr] = fmaxf(mx[rr], __shfl_xor_sync(0xffffffffu, mx[rr], o));
        #pragma unroll
        for (int rr = 0; rr < 4; rr++) {
            l0[rr] = __expf(l0[rr] - mx[rr]);
            l1[rr] = __expf(l1[rr] - mx[rr]);
            sms[rr] = l0[rr] + l1[rr];
        }
        #pragma unroll
        for (int o = 16; o; o >>= 1)
            #pragma unroll
            for (int rr = 0; rr < 4; rr++)
                sms[rr] += __shfl_xor_sync(0xffffffffu, sms[rr], o);

        float ss0 = 0.f, ss1 = 0.f;
        #pragma unroll
        for (int rr = 0; rr < 4; rr++) {
            int row = w * 4 + rr;
            float inv = 1.f / sms[rr];
            float r0 = l0[rr] * inv, r1 = l1[rr] * inv;
            sr[row * 64 + lane]      = r0;
            sr[row * 64 + lane + 32] = r1;
            ss0 += r0; ss1 += r1;
        }
        sS[w * 64 + lane]      = ss0;
        sS[w * 64 + lane + 32] = ss1;
    }
    __syncthreads();
    if (tid < 64) {      // cross-warp reduce, deterministic slot write
        float S = 0.f;
        #pragma unroll
        for (int ww = 0; ww < 8; ww++) S += sS[ww * 64 + tid];
        g_Ssl[(b * NSLOT + slot) * 64 + tid] = S;
    }

    // ---- Phase C: pool GEMM, 8k x 8d tiles, double-buffered (2 stages) ----
    ull acc2[32];
    #pragma unroll
    for (int i = 0; i < 32; i++) acc2[i] = 0ull;

    float4* xsb[2] = { (float4*)sm, (float4*)(sm + 16384) };

    float4 pc[4];
    #pragma unroll
    for (int ii = 0; ii < 4; ii++) {
        int idx = tid + 256 * ii;
        pc[ii] = x4[(trow0 + (idx >> 6)) * 64 + (idx & 63)];
    }
    {   // prologue: fill buf0 with stage 0, prefetch stage 1
        float4* xs0 = xsb[0];
        #pragma unroll
        for (int ii = 0; ii < 4; ii++) xs0[tid + 256 * ii] = pc[ii];
        #pragma unroll
        for (int ii = 0; ii < 4; ii++) {
            int idx = tid + 256 * ii;
            pc[ii] = x4[(trow0 + 16 + (idx >> 6)) * 64 + (idx & 63)];
        }
    }
    __syncthreads();

    #pragma unroll
    for (int st = 0; st < 2; st++) {
        if (st == 0) {   // store stage 1 early (hidden under compute)
            float4* xn = xsb[1];
            #pragma unroll
            for (int ii = 0; ii < 4; ii++) xn[tid + 256 * ii] = pc[ii];
        }
        const float4* xs = xsb[st];
        #pragma unroll
        for (int tt = 0; tt < 16; tt++) {
            const float* rk = &sr[(st * 16 + tt) * 64 + w * 8];
            ull rp[4];
            #pragma unroll
            for (int m = 0; m < 4; m++)
                rp[m] = *(const ull*)(rk + 2 * m);    // broadcast LDS.64
            F4 xa, xb;
            xa.f = xs[tt * 64 + lane];
            xb.f = xs[tt * 64 + 32 + lane];
            #pragma unroll
            for (int m = 0; m < 4; m++) {
                float2 rr = unpack2(rp[m]);
                ull r2a = pack2(rr.x, rr.x);
                ull r2b = pack2(rr.y, rr.y);
                int ka = (2 * m) * 4, kb = (2 * m + 1) * 4;
                acc2[ka + 0] = fma2(r2a, xa.u[0], acc2[ka + 0]);
                acc2[ka + 1] = fma2(r2a, xa.u[1], acc2[ka + 1]);
                acc2[ka + 2] = fma2(r2a, xb.u[0], acc2[ka + 2]);
                acc2[ka + 3] = fma2(r2a, xb.u[1], acc2[ka + 3]);
                acc2[kb + 0] = fma2(r2b, xa.u[0], acc2[kb + 0]);
                acc2[kb + 1] = fma2(r2b, xa.u[1], acc2[kb + 1]);
                acc2[kb + 2] = fma2(r2b, xb.u[0], acc2[kb + 2]);
                acc2[kb + 3] = fma2(r2b, xb.u[1], acc2[kb + 3]);
            }
        }
        if (st == 0) __syncthreads();
    }

    // no-return vector reductions into g_acc (re-zeroed by finalize)
    float* ob = g_acc + b * (KK * DD);
    #pragma unroll
    for (int kk = 0; kk < 8; kk++) {
        int kr = (w * 8 + kk) * DD + 4 * lane;
        float2 a0 = unpack2(acc2[kk * 4 + 0]), a1 = unpack2(acc2[kk * 4 + 1]);
        float2 b0 = unpack2(acc2[kk * 4 + 2]), b1 = unpack2(acc2[kk * 4 + 3]);
        red_add_v4(ob + kr,       a0.x, a0.y, a1.x, a1.y);   // d = 4*lane
        red_add_v4(ob + kr + 128, b0.x, b0.y, b1.x, b1.y);   // d = 128 + 4*lane
    }
}

// ---------------- finalize: out = (g_acc - mu*S)/(S+1e-9); re-zero g_acc --------
__global__ __launch_bounds__(512, 2)
void finalize_kernel(const float* __restrict__ mu, float* __restrict__ out) {
    __shared__ float sSsl[8 * NSLOT];
    __shared__ float sS[8];
    int tid = threadIdx.x;
    int bx  = blockIdx.x;          // 128 blocks
    int b   = bx >> 3;
    int k0  = (bx & 7) * 8;
    int i   = bx * 512 + tid;      // f4 index in [0, 65536)

    if (tid < 8 * NSLOT) {
        int kk = tid / NSLOT, s = tid - kk * NSLOT;   // parallel loads
        sSsl[tid] = g_Ssl[(b * NSLOT + s) * 64 + k0 + kk];
    }
    __syncthreads();
    if (tid < 8) {
        float S = 0.f;
        #pragma unroll
        for (int s = 0; s < NSLOT; s++) S += sSsl[tid * NSLOT + s];  // fixed order
        sS[tid] = S;
    }
    __syncthreads();

    float S = sS[tid >> 6];
    float inv = 1.f / (S + 1e-9f);
    float4 a = ((const float4*)g_acc)[i];
    float4 m = ((const float4*)mu)[i & 4095];
    float4 o;
    o.x = (a.x - m.x * S) * inv;
    o.y = (a.y - m.y * S) * inv;
    o.z = (a.z - m.z * S) * inv;
    o.w = (a.w - m.w * S) * inv;
    ((float4*)out)[i] = o;
    ((float4*)g_acc)[i] = make_float4(0.f, 0.f, 0.f, 0.f);   // self-clean
}

// ---------------- launcher --------------------------------------------------------
extern "C" void kernel_launch(void* const* d_in, const int* in_sizes, int n_in,
                              void* d_out, int out_size) {
    const float* x    = (const float*)d_in[0];
    const float* mu   = (const float*)d_in[1];
    const float* prec = (const float*)d_in[2];
    float* out = (float*)d_out;

    fused_kernel<<<BB * NSLOT, 256, FUSED_SMEM>>>(x, mu, prec);
    finalize_kernel<<<128, 512>>>(mu, out);
}

// round 13
// speedup vs baseline: 1.1832x; 1.1832x over previous
#include <cuda_runtime.h>

// Problem constants: x (16,800,256), mu (64,256), prec (64) -> out (16, 64*256)
#define BB 16
#define TT 800
#define DD 256
#define KK 64
#define NSLOT 9   // 8 blocks of 96 rows + 1 block of 32 rows per batch
#define PX 68     // smem pitch for sx/smu (16B-aligned rows, conflict-free)
#define PG 65     // smem pitch for sG (kills STS bank conflicts in dump)

typedef unsigned long long ull;

// ---------------- scratch (device globals) --------------------------------------
// Both zero at module load; finalize re-zeros after reading -> invariant across
// graph replays.
__device__ float g_acc[BB * KK * DD];   // pool accumulator (RED target)
__device__ float g_S[BB * KK];          // softmax-sum accumulator (RED target)

// ---------------- f32x2 / RED helpers -------------------------------------------
__device__ __forceinline__ ull pack2(float lo, float hi) {
    ull r; asm("mov.b64 %0,{%1,%2};" : "=l"(r) : "f"(lo), "f"(hi)); return r;
}
__device__ __forceinline__ ull fma2(ull a, ull b, ull c) {
    ull d; asm("fma.rn.f32x2 %0,%1,%2,%3;" : "=l"(d) : "l"(a), "l"(b), "l"(c)); return d;
}
__device__ __forceinline__ float2 unpack2(ull v) {
    float2 f; asm("mov.b64 {%0,%1},%2;" : "=f"(f.x), "=f"(f.y) : "l"(v)); return f;
}
__device__ __forceinline__ void red_add_v4(float* p, float x, float y, float z, float w) {
    asm volatile("red.global.add.v4.f32 [%0], {%1,%2,%3,%4};"
                 :: "l"(p), "f"(x), "f"(y), "f"(z), "f"(w) : "memory");
}
__device__ __forceinline__ void red_add_f32(float* p, float v) {
    asm volatile("red.global.add.f32 [%0], %1;" :: "l"(p), "f"(v) : "memory");
}

union F4 { float4 f; ull u[2]; };

// ---------------- fused body: llk GEMM + softmax + pool GEMM --------------------
template<int NR>
__device__ __forceinline__ void fused_body(int b, int slot, int trow0,
                                           const float* __restrict__ x,
                                           const float* __restrict__ mu,
                                           const float* __restrict__ prec) {
    constexpr int RT  = NR / 16;   // staging loads per thread
    constexpr int RPW = NR / 8;    // rows per warp (phase B)
    constexpr int RL  = NR / 32;   // rows per lane (phase A compute)
    constexpr int NST = NR / 16;   // phase C stages
    // phase C double-buffer offsets (bytes); NR=32 must dodge live sr region
    constexpr int XS1_OFF = (NR >= 96) ? 16384 : 40960;

    extern __shared__ char sm[];
    float* sx    = (float*)sm;             // NR*PX
    float* smu   = sx + NR * PX;           // 64*PX
    float* sr    = smu + 64 * PX;          // NR*64
    float* sxsq  = sr + NR * 64;           // NR
    float* smusq = sxsq + NR;              // 64
    float*  sG = sx;                       // phase B overlay: NR*PG <= NR*PX

    int tid  = threadIdx.x;
    int lane = tid & 31;
    int w    = tid >> 5;

    const float4* x4  = (const float4*)x;
    const float4* mu4 = (const float4*)mu;

    ull acc[RL * 8];
    #pragma unroll
    for (int i = 0; i < RL * 8; i++) acc[i] = 0ull;
    float myxsq[RT];
    #pragma unroll
    for (int i = 0; i < RT; i++) myxsq[i] = 0.f;
    float mymusq[4] = {0.f, 0.f, 0.f, 0.f};

    // prefetch chunk 0 (staging layout: 16 threads per row, j = tid&15)
    float4 px[RT], pm[4];
    #pragma unroll
    for (int ii = 0; ii < RT; ii++) {
        int idx = tid + 256 * ii;
        px[ii] = x4[(trow0 + (idx >> 4)) * 64 + (idx & 15)];
    }
    #pragma unroll
    for (int ii = 0; ii < 4; ii++) {
        int idx = tid + 256 * ii;
        pm[ii] = mu4[(idx >> 4) * 64 + (idx & 15)];
    }

    // ---- Phase A: distance GEMM over 4 chunks of 64 d ----
    for (int c = 0; c < 4; c++) {
        __syncthreads();
        #pragma unroll
        for (int ii = 0; ii < RT; ii++) {
            int idx = tid + 256 * ii;
            int r = idx >> 4, j = idx & 15;
            float4 v = px[ii];
            myxsq[ii] += v.x * v.x + v.y * v.y + v.z * v.z + v.w * v.w;
            *(float4*)(sx + r * PX + 4 * j) = v;
        }
        #pragma unroll
        for (int ii = 0; ii < 4; ii++) {
            int idx = tid + 256 * ii;
            int r = idx >> 4, j = idx & 15;
            float4 m = pm[ii];
            mymusq[ii] += m.x * m.x + m.y * m.y + m.z * m.z + m.w * m.w;
            *(float4*)(smu + r * PX + 4 * j) = m;
        }
        __syncthreads();
        if (c < 3) {   // prefetch next chunk while computing this one
            #pragma unroll
            for (int ii = 0; ii < RT; ii++) {
                int idx = tid + 256 * ii;
                px[ii] = x4[(trow0 + (idx >> 4)) * 64 + (c + 1) * 16 + (idx & 15)];
            }
            #pragma unroll
            for (int ii = 0; ii < 4; ii++) {
                int idx = tid + 256 * ii;
                pm[ii] = mu4[(idx >> 4) * 64 + (c + 1) * 16 + (idx & 15)];
            }
        }
        // compute: 16 iterations of 4 d (2 d-pairs) each
        #pragma unroll 2
        for (int q = 0; q < 16; q++) {
            F4 mv[8], xv[RL];
            #pragma unroll
            for (int j = 0; j < 8; j++)
                mv[j].f = *(const float4*)(smu + (w * 8 + j) * PX + 4 * q);  // broadcast
            #pragma unroll
            for (int i = 0; i < RL; i++)
                xv[i].f = *(const float4*)(sx + (lane + 32 * i) * PX + 4 * q);
            #pragma unroll
            for (int i = 0; i < RL; i++)
                #pragma unroll
                for (int j = 0; j < 8; j++) {
                    acc[i * 8 + j] = fma2(xv[i].u[0], mv[j].u[0], acc[i * 8 + j]);
                    acc[i * 8 + j] = fma2(xv[i].u[1], mv[j].u[1], acc[i * 8 + j]);
                }
        }
    }

    // reduce xsq / musq across the 16 threads sharing a staging row
    #pragma unroll
    for (int o = 1; o < 16; o <<= 1) {
        #pragma unroll
        for (int ii = 0; ii < RT; ii++)
            myxsq[ii] += __shfl_xor_sync(0xffffffffu, myxsq[ii], o);
        #pragma unroll
        for (int ii = 0; ii < 4; ii++)
            mymusq[ii] += __shfl_xor_sync(0xffffffffu, mymusq[ii], o);
    }
    __syncthreads();   // everyone done reading sx before sG overlay
    if ((tid & 15) == 0) {
        #pragma unroll
        for (int ii = 0; ii < RT; ii++) sxsq[(tid >> 4) + 16 * ii] = myxsq[ii];
        #pragma unroll
        for (int ii = 0; ii < 4; ii++)  smusq[(tid >> 4) + 16 * ii] = mymusq[ii];
    }

    // dump G tile (overlay on sx, pitch PG)
    #pragma unroll
    for (int i = 0; i < RL; i++) {
        int row = lane + 32 * i;
        #pragma unroll
        for (int j = 0; j < 8; j++) {
            float2 v = unpack2(acc[i * 8 + j]);
            sG[row * PG + w * 8 + j] = v.x + v.y;
        }
    }
    __syncthreads();

    // ---- Phase B: softmax over K (level-outer shfl loops for ILP) ----
    {
        float p0 = prec[lane], p1 = prec[lane + 32];
        float pp0 = p0 * p0, pp1 = p1 * p1;
        float mq0 = smusq[lane], mq1 = smusq[lane + 32];

        float l0[RPW], l1[RPW], mx[RPW], sms[RPW];
        #pragma unroll
        for (int rr = 0; rr < RPW; rr++) {
            int row = w * RPW + rr;
            float xq = sxsq[row];
            float G0 = sG[row * PG + lane];
            float G1 = sG[row * PG + lane + 32];
            l0[rr] = -pp0 * (xq - 2.f * G0 + mq0);
            l1[rr] = -pp1 * (xq - 2.f * G1 + mq1);
            mx[rr] = fmaxf(l0[rr], l1[rr]);
        }
        #pragma unroll
        for (int o = 16; o; o >>= 1)       // independent chains pipeline shfl lat
            #pragma unroll
            for (int rr = 0; rr < RPW; rr++)
                mx[rr] = fmaxf(mx[rr], __shfl_xor_sync(0xffffffffu, mx[rr], o));
        #pragma unroll
        for (int rr = 0; rr < RPW; rr++) {
            l0[rr] = __expf(l0[rr] - mx[rr]);
            l1[rr] = __expf(l1[rr] - mx[rr]);
            sms[rr] = l0[rr] + l1[rr];
        }
        #pragma unroll
        for (int o = 16; o; o >>= 1)
            #pragma unroll
            for (int rr = 0; rr < RPW; rr++)
                sms[rr] += __shfl_xor_sync(0xffffffffu, sms[rr], o);

        float ss0 = 0.f, ss1 = 0.f;
        #pragma unroll
        for (int rr = 0; rr < RPW; rr++) {
            int row = w * RPW + rr;
            float inv = 1.f / sms[rr];
            float r0 = l0[rr] * inv, r1 = l1[rr] * inv;
            sr[row * 64 + lane]      = r0;
            sr[row * 64 + lane + 32] = r1;
            ss0 += r0; ss1 += r1;
        }
        // per-warp fire-and-forget S accumulation (zeroed by finalize)
        red_add_f32(g_S + b * 64 + lane,      ss0);
        red_add_f32(g_S + b * 64 + lane + 32, ss1);
    }
    __syncthreads();   // sr visible to all warps before phase C reads it

    // ---- Phase C: pool GEMM, 8k x 8d tiles, double-buffered smem ----
    ull acc2[32];
    #pragma unroll
    for (int i = 0; i < 32; i++) acc2[i] = 0ull;

    float4* xsb[2] = { (float4*)sm, (float4*)(sm + XS1_OFF) };

    float4 pc[4];
    #pragma unroll
    for (int ii = 0; ii < 4; ii++) {
        int idx = tid + 256 * ii;
        pc[ii] = x4[(trow0 + (idx >> 6)) * 64 + (idx & 63)];
    }
    {   // prologue: fill buffer 0
        float4* xs0 = xsb[0];
        #pragma unroll
        for (int ii = 0; ii < 4; ii++) xs0[tid + 256 * ii] = pc[ii];
    }
    __syncthreads();

    for (int st = 0; st < NST; st++) {
        const float4* xs = xsb[st & 1];
        if (st + 1 < NST) {   // prefetch next stage into regs
            #pragma unroll
            for (int ii = 0; ii < 4; ii++) {
                int idx = tid + 256 * ii;
                pc[ii] = x4[(trow0 + (st + 1) * 16 + (idx >> 6)) * 64 + (idx & 63)];
            }
        }
        #pragma unroll
        for (int tt = 0; tt < 16; tt++) {
            const float* rk = &sr[(st * 16 + tt) * 64 + w * 8];
            ull rp[4];
            #pragma unroll
            for (int m = 0; m < 4; m++)
                rp[m] = *(const ull*)(rk + 2 * m);    // broadcast LDS.64
            F4 xa, xb;
            xa.f = xs[tt * 64 + lane];
            xb.f = xs[tt * 64 + 32 + lane];
            #pragma unroll
            for (int m = 0; m < 4; m++) {
                float2 rr = unpack2(rp[m]);
                ull r2a = pack2(rr.x, rr.x);
                ull r2b = pack2(rr.y, rr.y);
                int ka = (2 * m) * 4, kb = (2 * m + 1) * 4;
                acc2[ka + 0] = fma2(r2a, xa.u[0], acc2[ka + 0]);
                acc2[ka + 1] = fma2(r2a, xa.u[1], acc2[ka + 1]);
                acc2[ka + 2] = fma2(r2a, xb.u[0], acc2[ka + 2]);
                acc2[ka + 3] = fma2(r2a, xb.u[1], acc2[ka + 3]);
                acc2[kb + 0] = fma2(r2b, xa.u[0], acc2[kb + 0]);
                acc2[kb + 1] = fma2(r2b, xa.u[1], acc2[kb + 1]);
                acc2[kb + 2] = fma2(r2b, xb.u[0], acc2[kb + 2]);
                acc2[kb + 3] = fma2(r2b, xb.u[1], acc2[kb + 3]);
            }
        }
        if (st + 1 < NST) {   // store next stage into the other buffer
            float4* xn = xsb[(st + 1) & 1];
            #pragma unroll
            for (int ii = 0; ii < 4; ii++) xn[tid + 256 * ii] = pc[ii];
            __syncthreads();
        }
    }

    // no-return vector reductions into g_acc (re-zeroed by finalize)
    float* ob = g_acc + b * (KK * DD);
    #pragma unroll
    for (int kk = 0; kk < 8; kk++) {
        int kr = (w * 8 + kk) * DD + 4 * lane;
        float2 a0 = unpack2(acc2[kk * 4 + 0]), a1 = unpack2(acc2[kk * 4 + 1]);
        float2 b0 = unpack2(acc2[kk * 4 + 2]), b1 = unpack2(acc2[kk * 4 + 3]);
        red_add_v4(ob + kr,       a0.x, a0.y, a1.x, a1.y);   // d = 4*lane
        red_add_v4(ob + kr + 128, b0.x, b0.y, b1.x, b1.y);   // d = 128 + 4*lane
    }
}

__global__ __launch_bounds__(256, 1)
void fused_kernel(const float* __restrict__ x, const float* __restrict__ mu,
                  const float* __restrict__ prec) {
    int bx = blockIdx.x;
    if (bx < 128) {
        int b = bx >> 3, slot = bx & 7;
        fused_body<96>(b, slot, b * TT + slot * 96, x, mu, prec);
    } else {
        int b = bx - 128;
        fused_body<32>(b, 8, b * TT + 768, x, mu, prec);
    }
}

// smem: (96*68 + 64*68 + 96*64 + 96 + 64) * 4 + pad = 70784 bytes (round-10 layout)
#define FUSED_SMEM 70784

// ---------------- finalize: out = (g_acc - mu*S)/(S+1e-9); self-clean scratch ---
// 128 blocks x 512 threads; block covers batch b, k in [k0, k0+8).
// Chain: one broadcast g_S load -> independent g_acc/mu loads -> fma -> store.
__global__ __launch_bounds__(512, 2)
void finalize_kernel(const float* __restrict__ mu, float* __restrict__ out) {
    int tid = threadIdx.x;
    int bx  = blockIdx.x;
    int b   = bx >> 3;
    int k0  = (bx & 7) * 8;
    int i   = bx * 512 + tid;      // f4 index in [0, 65536)
    int k   = k0 + (tid >> 6);

    float S = g_S[b * 64 + k];
    float inv = 1.f / (S + 1e-9f);
    float4 a = ((const float4*)g_acc)[i];
    float4 m = ((const float4*)mu)[i & 4095];
    float4 o;
    o.x = (a.x - m.x * S) * inv;
    o.y = (a.y - m.y * S) * inv;
    o.z = (a.z - m.z * S) * inv;
    o.w = (a.w - m.w * S) * inv;
    ((float4*)out)[i] = o;
    ((float4*)g_acc)[i] = make_float4(0.f, 0.f, 0.f, 0.f);   // self-clean P

    __syncthreads();               // all S reads done before zeroing
    if (tid < 8) g_S[b * 64 + k0 + tid] = 0.f;                // self-clean S
}

// ---------------- launcher --------------------------------------------------------
extern "C" void kernel_launch(void* const* d_in, const int* in_sizes, int n_in,
                              void* d_out, int out_size) {
    const float* x    = (const float*)d_in[0];
    const float* mu   = (const float*)d_in[1];
    const float* prec = (const float*)d_in[2];
    float* out = (float*)d_out;

    cudaFuncSetAttribute(fused_kernel, cudaFuncAttributeMaxDynamicSharedMemorySize,
                         FUSED_SMEM);

    fused_kernel<<<144, 256, FUSED_SMEM>>>(x, mu, prec);
    finalize_kernel<<<128, 512>>>(mu, out);
}

// round 15
// speedup vs baseline: 1.1935x; 1.0087x over previous
#include <cuda_runtime.h>
#include <cuda_bf16.h>
#include <mma.h>
#include <cstdint>

using namespace nvcuda;

// Problem constants: x (16,800,256), mu (64,256), prec (64) -> out (16, 64*256)
#define BB 16
#define TT 800
#define DD 256
#define KK 64
#define PB  72    // bf16 pitch for split tiles (rows 144B, 32B-aligned tiles)
#define PGA 72    // f32 pitch for sG (ldm mult of 4, rows 288B = 9*32B aligned)

typedef unsigned long long ull;

// ---------------- scratch (device globals; self-cleaning across replays) --------
__device__ float g_acc[BB * KK * DD];   // pool accumulator (RED target)
__device__ float g_S[BB * KK];          // softmax-sum accumulator (RED target)

// ---------------- f32x2 / RED helpers -------------------------------------------
__device__ __forceinline__ ull pack2(float lo, float hi) {
    ull r; asm("mov.b64 %0,{%1,%2};" : "=l"(r) : "f"(lo), "f"(hi)); return r;
}
__device__ __forceinline__ ull fma2(ull a, ull b, ull c) {
    ull d; asm("fma.rn.f32x2 %0,%1,%2,%3;" : "=l"(d) : "l"(a), "l"(b), "l"(c)); return d;
}
__device__ __forceinline__ float2 unpack2(ull v) {
    float2 f; asm("mov.b64 {%0,%1},%2;" : "=f"(f.x), "=f"(f.y) : "l"(v)); return f;
}
__device__ __forceinline__ void red_add_v4(float* p, float x, float y, float z, float w) {
    asm volatile("red.global.add.v4.f32 [%0], {%1,%2,%3,%4};"
                 :: "l"(p), "f"(x), "f"(y), "f"(z), "f"(w) : "memory");
}
__device__ __forceinline__ void red_add_f32(float* p, float v) {
    asm volatile("red.global.add.f32 [%0], %1;" :: "l"(p), "f"(v) : "memory");
}

union F4 { float4 f; ull u[2]; };

// ---------------- bf16 3-split helpers -------------------------------------------
__device__ __forceinline__ float bftr(float v) {
    return __uint_as_float(__float_as_uint(v) & 0xFFFF0000u);
}
__device__ __forceinline__ uint32_t pbf(float a, float b) {   // {lo=bf(a), hi=bf(b)}
    uint32_t r;
    asm("prmt.b32 %0, %1, %2, 0x7632;" : "=r"(r)
        : "r"(__float_as_uint(a)), "r"(__float_as_uint(b)));
    return r;
}
// split a float4 into 3 packed-bf16 ulls (h, m, l)
__device__ __forceinline__ void split3(float4 v, ull& uh, ull& um, ull& ul) {
    float h0 = bftr(v.x), r0 = v.x - h0, m0 = bftr(r0), l0 = bftr(r0 - m0);
    float h1 = bftr(v.y), r1 = v.y - h1, m1 = bftr(r1), l1 = bftr(r1 - m1);
    float h2 = bftr(v.z), r2 = v.z - h2, m2 = bftr(r2), l2 = bftr(r2 - m2);
    float h3 = bftr(v.w), r3 = v.w - h3, m3 = bftr(r3), l3 = bftr(r3 - m3);
    uh = (ull)pbf(h0, h1) | ((ull)pbf(h2, h3) << 32);
    um = (ull)pbf(m0, m1) | ((ull)pbf(m2, m3) << 32);
    ul = (ull)pbf(l0, l1) | ((ull)pbf(l2, l3) << 32);
}

// split-product pairs (a-split, b-split): all of {0,1,2}^2 except (2,2)
__device__ __constant__ const int PAIR_A[8] = {0, 0, 1, 0, 2, 1, 1, 2};
__device__ __constant__ const int PAIR_B[8] = {0, 1, 0, 2, 0, 1, 2, 1};

#define OFF_SR   73728
#define OFF_XSQ  99840
#define OFF_MUSQ 100224
#define FUSED_SMEM 100864

// ---------------- fused body: WMMA llk GEMM + softmax + SIMT pool GEMM ----------
template<int NR>
__device__ __forceinline__ void fused_body(int b, int trow0,
                                           const float* __restrict__ x,
                                           const float* __restrict__ mu,
                                           const float* __restrict__ prec) {
    constexpr int RT  = NR / 16;   // X staging float4s per thread per chunk
    constexpr int RPW = NR / 8;    // rows per warp (phase B)
    constexpr int NST = NR / 16;   // phase C stages
    constexpr int TPW = NR / 32;   // mtiles per warp (96->3, 32->1)
    constexpr int XSPB = NR * PB * 2;   // bytes per X split plane
    constexpr int MSPB = 64 * PB * 2;   // bytes per MU split plane

    extern __shared__ char sm[];
    char* xsp[3] = { sm, sm + XSPB, sm + 2 * XSPB };
    char* msp[3] = { sm + 3 * XSPB, sm + 3 * XSPB + MSPB, sm + 3 * XSPB + 2 * MSPB };
    float* sG    = (float*)sm;                 // overlay after phase A mma
    float* sr    = (float*)(sm + OFF_SR);      // NR x 64 (pitch 64)
    float* sxsq  = (float*)(sm + OFF_XSQ);
    float* smusq = (float*)(sm + OFF_MUSQ);

    int tid  = threadIdx.x;
    int lane = tid & 31;
    int w    = tid >> 5;
    int wr   = w >> 2;     // 0..1
    int wc   = w & 3;      // 0..3 -> ntile

    const float4* x4  = (const float4*)x;
    const float4* mu4 = (const float4*)mu;

    float myxsq[RT];
    #pragma unroll
    for (int i = 0; i < RT; i++) myxsq[i] = 0.f;
    float mymusq[4] = {0.f, 0.f, 0.f, 0.f};

    // prefetch chunk 0 (16 threads per row, j = tid&15 -> 4 d each)
    float4 px[RT], pm[4];
    #pragma unroll
    for (int ii = 0; ii < RT; ii++) {
        int idx = tid + 256 * ii;
        px[ii] = x4[(trow0 + (idx >> 4)) * 64 + (idx & 15)];
    }
    #pragma unroll
    for (int ii = 0; ii < 4; ii++) {
        int idx = tid + 256 * ii;
        pm[ii] = mu4[(idx >> 4) * 64 + (idx & 15)];
    }

    wmma::fragment<wmma::accumulator, 16, 16, 16, float> fc[TPW];
    #pragma unroll
    for (int t = 0; t < TPW; t++) wmma::fill_fragment(fc[t], 0.f);

    // ---- Phase A: 4 chunks of 64 d; split-stage, WMMA accumulate ----
    for (int c = 0; c < 4; c++) {
        // stage splits into smem (pitch PB bf16, rows 144B)
        #pragma unroll
        for (int ii = 0; ii < RT; ii++) {
            int idx = tid + 256 * ii;
            int row = idx >> 4, j = idx & 15;
            float4 v = px[ii];
            myxsq[ii] += v.x * v.x + v.y * v.y + v.z * v.z + v.w * v.w;
            ull uh, um, ul;
            split3(v, uh, um, ul);
            uint32_t off = (uint32_t)(row * (PB * 2) + j * 8);
            *(ull*)(xsp[0] + off) = uh;
            *(ull*)(xsp[1] + off) = um;
            *(ull*)(xsp[2] + off) = ul;
        }
        #pragma unroll
        for (int ii = 0; ii < 4; ii++) {
            int idx = tid + 256 * ii;
            int row = idx >> 4, j = idx & 15;
            float4 v = pm[ii];
            mymusq[ii] += v.x * v.x + v.y * v.y + v.z * v.z + v.w * v.w;
            ull uh, um, ul;
            split3(v, uh, um, ul);
            uint32_t off = (uint32_t)(row * (PB * 2) + j * 8);
            *(ull*)(msp[0] + off) = uh;
            *(ull*)(msp[1] + off) = um;
            *(ull*)(msp[2] + off) = ul;
        }
        if (c < 3) {   // prefetch next chunk (lands during mma)
            #pragma unroll
            for (int ii = 0; ii < RT; ii++) {
                int idx = tid + 256 * ii;
                px[ii] = x4[(trow0 + (idx >> 4)) * 64 + (c + 1) * 16 + (idx & 15)];
            }
            #pragma unroll
            for (int ii = 0; ii < 4; ii++) {
                int idx = tid + 256 * ii;
                pm[ii] = mu4[(idx >> 4) * 64 + (c + 1) * 16 + (idx & 15)];
            }
        }
        __syncthreads();

        // WMMA: 4 k-steps of 16; warp (wr,wc): mtiles wr*TPW+t, ntile wc
        #pragma unroll
        for (int ks = 0; ks < 4; ks++) {
            wmma::fragment<wmma::matrix_b, 16, 16, 16, __nv_bfloat16,
                           wmma::col_major> fb[3];
            #pragma unroll
            for (int s = 0; s < 3; s++)
                wmma::load_matrix_sync(fb[s],
                    (const __nv_bfloat16*)(msp[s]) + wc * 16 * PB + ks * 16, PB);
            wmma::fragment<wmma::matrix_a, 16, 16, 16, __nv_bfloat16,
                           wmma::row_major> fa[TPW][3];
            #pragma unroll
            for (int t = 0; t < TPW; t++) {
                int mt = wr * TPW + t;
                #pragma unroll
                for (int s = 0; s < 3; s++)
                    wmma::load_matrix_sync(fa[t][s],
                        (const __nv_bfloat16*)(xsp[s]) + mt * 16 * PB + ks * 16, PB);
            }
            #pragma unroll
            for (int p = 0; p < 8; p++) {          // pair-outer, t-inner (ILP)
                int sa = PAIR_A[p], sb = PAIR_B[p];
                #pragma unroll
                for (int t = 0; t < TPW; t++)
                    wmma::mma_sync(fc[t], fa[t][sa], fb[sb], fc[t]);
            }
        }
        __syncthreads();   // mma reads done before next chunk's staging
    }

    // xsq / musq reduce across the 16 staging threads per row
    #pragma unroll
    for (int o = 1; o < 16; o <<= 1) {
        #pragma unroll
        for (int ii = 0; ii < RT; ii++)
            myxsq[ii] += __shfl_xor_sync(0xffffffffu, myxsq[ii], o);
        #pragma unroll
        for (int ii = 0; ii < 4; ii++)
            mymusq[ii] += __shfl_xor_sync(0xffffffffu, mymusq[ii], o);
    }
    if ((tid & 15) == 0) {
        #pragma unroll
        for (int ii = 0; ii < RT; ii++) sxsq[(tid >> 4) + 16 * ii] = myxsq[ii];
        #pragma unroll
        for (int ii = 0; ii < 4; ii++)  smusq[(tid >> 4) + 16 * ii] = mymusq[ii];
    }

    // dump G tiles to sG (overlay on split region — splits dead now)
    #pragma unroll
    for (int t = 0; t < TPW; t++) {
        int mt = wr * TPW + t;
        wmma::store_matrix_sync(sG + mt * 16 * PGA + wc * 16, fc[t], PGA,
                                wmma::mem_row_major);
    }
    __syncthreads();

    // ---- Phase B: softmax over K (level-outer shfl loops for ILP) ----
    {
        float p0 = prec[lane], p1 = prec[lane + 32];
        float pp0 = p0 * p0, pp1 = p1 * p1;
        float mq0 = smusq[lane], mq1 = smusq[lane + 32];

        float l0[RPW], l1[RPW], mx[RPW], sms[RPW];
        #pragma unroll
        for (int rr = 0; rr < RPW; rr++) {
            int row = w * RPW + rr;
            float xq = sxsq[row];
            float G0 = sG[row * PGA + lane];
            float G1 = sG[row * PGA + lane + 32];
            l0[rr] = -pp0 * (xq - 2.f * G0 + mq0);
            l1[rr] = -pp1 * (xq - 2.f * G1 + mq1);
            mx[rr] = fmaxf(l0[rr], l1[rr]);
        }
        #pragma unroll
        for (int o = 16; o; o >>= 1)
            #pragma unroll
            for (int rr = 0; rr < RPW; rr++)
                mx[rr] = fmaxf(mx[rr], __shfl_xor_sync(0xffffffffu, mx[rr], o));
        #pragma unroll
        for (int rr = 0; rr < RPW; rr++) {
            l0[rr] = __expf(l0[rr] - mx[rr]);
            l1[rr] = __expf(l1[rr] - mx[rr]);
            sms[rr] = l0[rr] + l1[rr];
        }
        #pragma unroll
        for (int o = 16; o; o >>= 1)
            #pragma unroll
            for (int rr = 0; rr < RPW; rr++)
                sms[rr] += __shfl_xor_sync(0xffffffffu, sms[rr], o);

        float ss0 = 0.f, ss1 = 0.f;
        #pragma unroll
        for (int rr = 0; rr < RPW; rr++) {
            int row = w * RPW + rr;
            float inv = 1.f / sms[rr];
            float r0 = l0[rr] * inv, r1 = l1[rr] * inv;
            sr[row * 64 + lane]      = r0;
            sr[row * 64 + lane + 32] = r1;
            ss0 += r0; ss1 += r1;
        }
        red_add_f32(g_S + b * 64 + lane,      ss0);
        red_add_f32(g_S + b * 64 + lane + 32, ss1);
    }
    __syncthreads();   // sr visible before phase C

    // ---- Phase C: pool GEMM (SIMT f32x2), 8k x 8d tiles, double-buffered ----
    ull acc2[32];
    #pragma unroll
    for (int i = 0; i < 32; i++) acc2[i] = 0ull;

    float4* xsb[2] = { (float4*)sm, (float4*)(sm + 16384) };

    float4 pc[4];
    #pragma unroll
    for (int ii = 0; ii < 4; ii++) {
        int idx = tid + 256 * ii;
        pc[ii] = x4[(trow0 + (idx >> 6)) * 64 + (idx & 63)];
    }
    {
        float4* xs0 = xsb[0];
        #pragma unroll
        for (int ii = 0; ii < 4; ii++) xs0[tid + 256 * ii] = pc[ii];
    }
    __syncthreads();

    for (int st = 0; st < NST; st++) {
        const float4* xs = xsb[st & 1];
        if (st + 1 < NST) {
            #pragma unroll
            for (int ii = 0; ii < 4; ii++) {
                int idx = tid + 256 * ii;
                pc[ii] = x4[(trow0 + (st + 1) * 16 + (idx >> 6)) * 64 + (idx & 63)];
            }
        }
        #pragma unroll
        for (int tt = 0; tt < 16; tt++) {
            const float* rk = sr + (st * 16 + tt) * 64 + w * 8;
            ull rp[4];
            #pragma unroll
            for (int m = 0; m < 4; m++)
                rp[m] = *(const ull*)(rk + 2 * m);    // broadcast LDS.64
            F4 xa, xb;
            xa.f = xs[tt * 64 + lane];
            xb.f = xs[tt * 64 + 32 + lane];
            #pragma unroll
            for (int m = 0; m < 4; m++) {
                float2 rr = unpack2(rp[m]);
                ull r2a = pack2(rr.x, rr.x);
                ull r2b = pack2(rr.y, rr.y);
                int ka = (2 * m) * 4, kb = (2 * m + 1) * 4;
                acc2[ka + 0] = fma2(r2a, xa.u[0], acc2[ka + 0]);
                acc2[ka + 1] = fma2(r2a, xa.u[1], acc2[ka + 1]);
                acc2[ka + 2] = fma2(r2a, xb.u[0], acc2[ka + 2]);
                acc2[ka + 3] = fma2(r2a, xb.u[1], acc2[ka + 3]);
                acc2[kb + 0] = fma2(r2b, xa.u[0], acc2[kb + 0]);
                acc2[kb + 1] = fma2(r2b, xa.u[1], acc2[kb + 1]);
                acc2[kb + 2] = fma2(r2b, xb.u[0], acc2[kb + 2]);
                acc2[kb + 3] = fma2(r2b, xb.u[1], acc2[kb + 3]);
            }
        }
        if (st + 1 < NST) {
            float4* xn = xsb[(st + 1) & 1];
            #pragma unroll
            for (int ii = 0; ii < 4; ii++) xn[tid + 256 * ii] = pc[ii];
            __syncthreads();
        }
    }

    // vector reductions into g_acc (re-zeroed by finalize)
    float* ob = g_acc + b * (KK * DD);
    #pragma unroll
    for (int kk = 0; kk < 8; kk++) {
        int kr = (w * 8 + kk) * DD + 4 * lane;
        float2 a0 = unpack2(acc2[kk * 4 + 0]), a1 = unpack2(acc2[kk * 4 + 1]);
        float2 b0 = unpack2(acc2[kk * 4 + 2]), b1 = unpack2(acc2[kk * 4 + 3]);
        red_add_v4(ob + kr,       a0.x, a0.y, a1.x, a1.y);
        red_add_v4(ob + kr + 128, b0.x, b0.y, b1.x, b1.y);
    }
}

__global__ __launch_bounds__(256, 1)
void fused_kernel(const float* __restrict__ x, const float* __restrict__ mu,
                  const float* __restrict__ prec) {
    int bx = blockIdx.x;
    if (bx < 128) {
        int b = bx >> 3;
        fused_body<96>(b, b * TT + (bx & 7) * 96, x, mu, prec);
    } else {
        int b = bx - 128;
        fused_body<32>(b, b * TT + 768, x, mu, prec);
    }
}

// ---------------- finalize: out = (g_acc - mu*S)/(S+1e-9); self-clean -----------
__global__ __launch_bounds__(512, 2)
void finalize_kernel(const float* __restrict__ mu, float* __restrict__ out) {
    int tid = threadIdx.x;
    int bx  = blockIdx.x;
    int b   = bx >> 3;
    int k0  = (bx & 7) * 8;
    int i   = bx * 512 + tid;
    int k   = k0 + (tid >> 6);

    float S = g_S[b * 64 + k];
    float inv = 1.f / (S + 1e-9f);
    float4 a = ((const float4*)g_acc)[i];
    float4 m = ((const float4*)mu)[i & 4095];
    float4 o;
    o.x = (a.x - m.x * S) * inv;
    o.y = (a.y - m.y * S) * inv;
    o.z = (a.z - m.z * S) * inv;
    o.w = (a.w - m.w * S) * inv;
    ((float4*)out)[i] = o;
    ((float4*)g_acc)[i] = make_float4(0.f, 0.f, 0.f, 0.f);

    __syncthreads();
    if (tid < 8) g_S[b * 64 + k0 + tid] = 0.f;
}

// ---------------- launcher --------------------------------------------------------
extern "C" void kernel_launch(void* const* d_in, const int* in_sizes, int n_in,
                              void* d_out, int out_size) {
    const float* x    = (const float*)d_in[0];
    const float* mu   = (const float*)d_in[1];
    const float* prec = (const float*)d_in[2];
    float* out = (float*)d_out;

    cudaFuncSetAttribute(fused_kernel, cudaFuncAttributeMaxDynamicSharedMemorySize,
                         FUSED_SMEM);

    fused_kernel<<<144, 256, FUSED_SMEM>>>(x, mu, prec);
    finalize_kernel<<<128, 512>>>(mu, out);
}